// round 10
// baseline (speedup 1.0000x reference)
#include <cuda_runtime.h>
#include <cstdint>

#define HID    256
#define BATCH  8
#define NA     2048
#define NB     2048
#define FM     128
#define FN     32
#define NT     (NB / FN)       // 64 tiles

// tf32-rounded copies of inputs (round_kernel output, proj input)
__device__ float g_Ar[(size_t)BATCH * NA * HID];
__device__ float g_Br[(size_t)BATCH * NB * HID];
__device__ float g_Wr[3 * HID * HID];
// Projection outputs: Q,K row-major (Q pre-scaled 1/16), V transposed; all tf32-rounded fp32.
__device__ float g_Q [(size_t)BATCH * NA * HID];
__device__ float g_K [(size_t)BATCH * NB * HID];
__device__ float g_Vt[(size_t)BATCH * HID * NB];

// ---------------- helpers ----------------
__device__ __forceinline__ float tf32r(float x) {
    uint32_t r;
    asm("cvt.rna.tf32.f32 %0, %1;" : "=r"(r) : "f"(x));
    return __uint_as_float(r);
}
__device__ __forceinline__ uint32_t tf32u(float x) {
    uint32_t r;
    asm("cvt.rna.tf32.f32 %0, %1;" : "=r"(r) : "f"(x));
    return r;
}
__device__ __forceinline__ uint32_t smem_u32(const void* p) {
    uint32_t a;
    asm("{ .reg .u64 t; cvta.to.shared.u64 t, %1; cvt.u32.u64 %0, t; }"
        : "=r"(a) : "l"(p));
    return a;
}
__device__ __forceinline__ void ldsm4(uint32_t* r, uint32_t addr) {
    asm volatile("ldmatrix.sync.aligned.m8n8.x4.shared.b16 {%0,%1,%2,%3}, [%4];"
                 : "=r"(r[0]), "=r"(r[1]), "=r"(r[2]), "=r"(r[3]) : "r"(addr));
}
// tf32 k8 mma. A regs in (r0,r2,r1,r3) order (validated R5-R7).
__device__ __forceinline__ void mma8(float* c, const uint32_t* r,
                                     uint32_t b0, uint32_t b1) {
    asm volatile(
        "mma.sync.aligned.m16n8k8.row.col.f32.tf32.tf32.f32 "
        "{%0,%1,%2,%3}, {%4,%5,%6,%7}, {%8,%9}, {%0,%1,%2,%3};"
        : "+f"(c[0]), "+f"(c[1]), "+f"(c[2]), "+f"(c[3])
        : "r"(r[0]), "r"(r[2]), "r"(r[1]), "r"(r[3]), "r"(b0), "r"(b1));
}
__device__ __forceinline__ void cp16(uint32_t saddr, const void* g) {
    asm volatile("cp.async.cg.shared.global [%0], [%1], 16;"
                 :: "r"(saddr), "l"(g) : "memory");
}
#define CP_COMMIT() asm volatile("cp.async.commit_group;" ::: "memory")
#define CP_WAIT(N)  asm volatile("cp.async.wait_group %0;" :: "n"(N) : "memory")
__device__ __forceinline__ void sts_v2(uint32_t addr, uint32_t a, uint32_t b) {
    asm volatile("st.shared.v2.b32 [%0], {%1,%2};" :: "r"(addr), "r"(a), "r"(b)
                 : "memory");
}

// ---------------- round_kernel: rna-round A, B, W into scratch ----------------
#define N_AB4 ((BATCH * NA * HID) / 4)
#define N_W4  ((HID * HID) / 4)
#define N_TOT4 (2 * N_AB4 + 3 * N_W4)

__global__ __launch_bounds__(256) void round_kernel(
    const float* __restrict__ A, const float* __restrict__ B,
    const float* __restrict__ Wq, const float* __restrict__ Wk,
    const float* __restrict__ Wv)
{
    for (int i = blockIdx.x * 256 + threadIdx.x; i < N_TOT4;
         i += gridDim.x * 256) {
        const float4* src;
        float4* dst;
        if (i < N_AB4) {
            src = (const float4*)A + i;            dst = (float4*)g_Ar + i;
        } else if (i < 2 * N_AB4) {
            src = (const float4*)B + (i - N_AB4);  dst = (float4*)g_Br + (i - N_AB4);
        } else {
            int j = i - 2 * N_AB4;
            if (j < N_W4)          { src = (const float4*)Wq + j;
                                     dst = (float4*)g_Wr + j; }
            else if (j < 2 * N_W4) { src = (const float4*)Wk + (j - N_W4);
                                     dst = (float4*)(g_Wr + HID * HID) + (j - N_W4); }
            else                   { src = (const float4*)Wv + (j - 2 * N_W4);
                                     dst = (float4*)(g_Wr + 2 * HID * HID) + (j - 2 * N_W4); }
        }
        float4 v = *src;
        v.x = tf32r(v.x); v.y = tf32r(v.y); v.z = tf32r(v.z); v.w = tf32r(v.w);
        *dst = v;
    }
}

// ---------------- proj: tf32 mma GEMM (validated R6/R7) ----------------
#define PXLD 36
#define PJ_XS(buf) ((buf) * 4608)
#define PJ_WS(buf) (9216 + (buf) * 2304)
#define PJ_CLD 68
#define PJ_SMEM_BYTES (13824 * 4)

__global__ __launch_bounds__(256, 2) void proj_kernel(
    const float* __restrict__ bq, const float* __restrict__ bk,
    const float* __restrict__ bv)
{
    extern __shared__ float sm[];
    const uint32_t smb = smem_u32(sm);

    const int z = blockIdx.z;
    const int b = z & 7;
    const int which = z >> 3;

    const float* X = ((which == 0) ? g_Ar : g_Br) + (size_t)b * NA * HID;
    const float* W = g_Wr + which * HID * HID;
    const float* bias = (which == 0) ? bq : (which == 1) ? bk : bv;

    const int m0 = blockIdx.x * 128;
    const int h0 = blockIdx.y * 64;

    const int tid  = threadIdx.x;
    const int lane = tid & 31;
    const int wid  = tid >> 5;
    const int mw   = wid & 3;
    const int nh   = wid >> 2;
    const int g    = lane >> 2;
    const int tg   = lane & 3;
    const int lsrow = (lane & 7) + 8 * (lane >> 4);
    const int lscol = 4 * ((lane >> 3) & 1);

    float c[8][4];
    #pragma unroll
    for (int i = 0; i < 8; i++)
        #pragma unroll
        for (int j = 0; j < 4; j++) c[i][j] = 0.f;

    auto load_chunk = [&](int kc, int buf) {
        const int k0 = kc * 32;
        #pragma unroll
        for (int i = 0; i < 4; i++) {
            const int cc = tid + i * 256;
            const int r = cc >> 3, c4 = cc & 7;
            cp16(smb + (PJ_XS(buf) + r * PXLD + c4 * 4) * 4,
                 X + (size_t)(m0 + r) * HID + k0 + c4 * 4);
        }
        #pragma unroll
        for (int i = 0; i < 2; i++) {
            const int cc = tid + i * 256;
            const int r = cc >> 3, c4 = cc & 7;
            cp16(smb + (PJ_WS(buf) + r * PXLD + c4 * 4) * 4,
                 W + (size_t)(h0 + r) * HID + k0 + c4 * 4);
        }
    };

    load_chunk(0, 0); CP_COMMIT();

    for (int kc = 0; kc < 8; kc++) {
        if (kc < 7) load_chunk(kc + 1, (kc + 1) & 1);
        CP_COMMIT();
        CP_WAIT(1);
        __syncthreads();

        const int buf = kc & 1;
        const uint32_t aX = smb + (PJ_XS(buf) + (mw * 32 + lsrow) * PXLD + lscol) * 4;
        const uint32_t bW = smb + (PJ_WS(buf) + (nh * 32 + lsrow) * PXLD + lscol) * 4;

        #pragma unroll
        for (int ks = 0; ks < 4; ks++) {
            uint32_t a0[4], a1[4], b0[4], b1[4];
            ldsm4(a0, aX + ks * 32);
            ldsm4(a1, aX + 16 * PXLD * 4 + ks * 32);
            ldsm4(b0, bW + ks * 32);
            ldsm4(b1, bW + 16 * PXLD * 4 + ks * 32);
            mma8(c[0], a0, b0[0], b0[1]);  mma8(c[1], a0, b0[2], b0[3]);
            mma8(c[2], a0, b1[0], b1[1]);  mma8(c[3], a0, b1[2], b1[3]);
            mma8(c[4], a1, b0[0], b0[1]);  mma8(c[5], a1, b0[2], b0[3]);
            mma8(c[6], a1, b1[0], b1[1]);  mma8(c[7], a1, b1[2], b1[3]);
        }
        __syncthreads();
    }

    #pragma unroll
    for (int ms = 0; ms < 2; ms++)
        #pragma unroll
        for (int nb = 0; nb < 4; nb++) {
            const int row = mw * 32 + ms * 16 + g;
            const int col = nh * 32 + nb * 8 + 2 * tg;
            sts_v2(smb + (row * PJ_CLD + col) * 4,
                   __float_as_uint(c[ms * 4 + nb][0]),
                   __float_as_uint(c[ms * 4 + nb][1]));
            sts_v2(smb + ((row + 8) * PJ_CLD + col) * 4,
                   __float_as_uint(c[ms * 4 + nb][2]),
                   __float_as_uint(c[ms * 4 + nb][3]));
        }
    __syncthreads();

    if (which < 2) {
        float* out = ((which == 0) ? g_Q : g_K) + (size_t)b * NA * HID;
        const float qs = (which == 0) ? 0.0625f : 1.0f;
        #pragma unroll
        for (int i = 0; i < 8; i++) {
            const int cc = tid + i * 256;
            const int r = cc >> 4, c4 = cc & 15;
            const float* s = &sm[r * PJ_CLD + c4 * 4];
            const int h = h0 + c4 * 4;
            float4 o;
            o.x = tf32r((s[0] + bias[h + 0]) * qs);
            o.y = tf32r((s[1] + bias[h + 1]) * qs);
            o.z = tf32r((s[2] + bias[h + 2]) * qs);
            o.w = tf32r((s[3] + bias[h + 3]) * qs);
            *(float4*)&out[(size_t)(m0 + r) * HID + h] = o;
        }
    } else {
        float* out_t = g_Vt + (size_t)b * HID * NB;
        #pragma unroll
        for (int hh = 0; hh < 8; hh++) {
            const int h = wid * 8 + hh;
            const float bb = bias[h0 + h];
            float4 o;
            o.x = tf32r(sm[(lane * 4 + 0) * PJ_CLD + h] + bb);
            o.y = tf32r(sm[(lane * 4 + 1) * PJ_CLD + h] + bb);
            o.z = tf32r(sm[(lane * 4 + 2) * PJ_CLD + h] + bb);
            o.w = tf32r(sm[(lane * 4 + 3) * PJ_CLD + h] + bb);
            *(float4*)&out_t[(size_t)(h0 + h) * NB + m0 + lane * 4] = o;
        }
    }
}

// ---------------- attention smem layout (float indices; R7-validated) ----------------
#define QLD 260
#define KLD 260
#define VLD 36
#define PLD 36
#define QS_F 0                        // 128 x 260 = 33280
#define KS_F 33280                    // 32 x 260  = 8320
#define VS_F 41600                    // 256 x 36  = 9216
#define PS_F 50816                    // 128 x 36  = 4608
#define MK_F 55424                    // 2048
#define LR_F 57472                    // 128
#define SMEM_FLOATS 57728
#define SMEM_BYTES  (SMEM_FLOATS * 4) // 230912 <= 232448

#define NTH 512

__device__ __forceinline__ void load_Qt(uint32_t smb, const float* Qb, int q0, int tid) {
    #pragma unroll
    for (int i = 0; i < 16; i++) {
        const int cc = tid + i * NTH;
        const int r = cc >> 6, c4 = cc & 63;
        cp16(smb + (QS_F + r * QLD + c4 * 4) * 4,
             Qb + (size_t)(q0 + r) * HID + c4 * 4);
    }
}
__device__ __forceinline__ void load_Kt(uint32_t smb, const float* Kb, int n0, int tid) {
    #pragma unroll
    for (int i = 0; i < 4; i++) {
        const int cc = tid + i * NTH;
        const int r = cc >> 6, c4 = cc & 63;
        cp16(smb + (KS_F + r * KLD + c4 * 4) * 4,
             Kb + (size_t)(n0 + r) * HID + c4 * 4);
    }
}
__device__ __forceinline__ void load_Vt(uint32_t smb, const float* Vtb, int n0, int tid) {
    #pragma unroll
    for (int i = 0; i < 4; i++) {
        const int cc = tid + i * NTH;
        const int h = cc >> 3, c4 = cc & 7;
        cp16(smb + (VS_F + h * VLD + c4 * 4) * 4,
             Vtb + (size_t)h * NB + n0 + c4 * 4);
    }
}

// ---------------- attention: 512 threads; S by 4 warps (m32n32), PV by 16 ----------------
__global__ __launch_bounds__(NTH, 1) void attn_kernel(
    const int* __restrict__ maskB, float* __restrict__ out)
{
    extern __shared__ float sm[];
    const uint32_t smb = smem_u32(sm);

    const int tid  = threadIdx.x;
    const int lane = tid & 31;
    const int wid  = tid >> 5;
    const int mt   = wid & 7;    // PV: m16 tile (8 tiles = 128 rows)
    const int nh   = wid >> 3;   // PV: h-half(128)
    const int g    = lane >> 2;
    const int tg   = lane & 3;
    const int lsrow = (lane & 7) + 8 * (lane >> 4);
    const int lscol = 4 * ((lane >> 3) & 1);

    const int b  = blockIdx.y;
    const int q0 = blockIdx.x * FM;

    const float* Qb  = g_Q  + (size_t)b * NA * HID;
    const float* Kb  = g_K  + (size_t)b * NB * HID;
    const float* Vtb = g_Vt + (size_t)b * HID * NB;
    const int*   mk  = maskB + b * NB;

    for (int i = tid; i < NB; i += NTH) sm[MK_F + i] = (mk[i] != 0) ? 1.f : 0.f;

    // prologue: [Q + K0] group, then [V0] group
    load_Qt(smb, Qb, q0, tid);
    load_Kt(smb, Kb, 0, tid);              CP_COMMIT();
    load_Vt(smb, Vtb, 0, tid);             CP_COMMIT();

    // S-phase addresses (wid < 4 only; warp owns rows wid*32..wid*32+31, all 32 cols)
    const uint32_t aQ0 = smb + (QS_F + (wid * 32 + lsrow) * QLD + lscol) * 4;
    const uint32_t aQ1 = aQ0 + 16 * QLD * 4;
    const uint32_t bK0 = smb + (KS_F + lsrow * KLD + lscol) * 4;
    const uint32_t bK1 = bK0 + 16 * KLD * 4;
    // PV addresses (all 16 warps)
    const uint32_t aP  = smb + (PS_F + (mt * 16 + lsrow) * PLD + lscol) * 4;
    const uint32_t bV  = smb + (VS_F + (nh * 128 + lsrow) * VLD + lscol) * 4;

    float o[16][4];
    #pragma unroll
    for (int n = 0; n < 16; n++)
        #pragma unroll
        for (int j = 0; j < 4; j++) o[n][j] = 0.f;
    float lgA[2] = {0.f, 0.f}, lgB[2] = {0.f, 0.f};   // S-warp row sums (rows g, g+8 per ma)

    for (int t = 0; t < NT; t++) {
        CP_WAIT(1);                 // K_t (and Q at t=0) resident
        __syncthreads();

        if (wid < 4) {
            // ---- S = Q K_t^T : warp m32 x n32 (k8 steps) ----
            float c[2][4][4];
            #pragma unroll
            for (int ma = 0; ma < 2; ma++)
                #pragma unroll
                for (int nb = 0; nb < 4; nb++)
                    #pragma unroll
                    for (int j = 0; j < 4; j++) c[ma][nb][j] = 0.f;

            #pragma unroll
            for (int ks = 0; ks < 32; ks++) {
                uint32_t a0[4], a1[4], b0[4], b1[4];
                ldsm4(a0, aQ0 + ks * 32);
                ldsm4(a1, aQ1 + ks * 32);
                ldsm4(b0, bK0 + ks * 32);
                ldsm4(b1, bK1 + ks * 32);
                mma8(c[0][0], a0, b0[0], b0[1]);  mma8(c[0][1], a0, b0[2], b0[3]);
                mma8(c[0][2], a0, b1[0], b1[1]);  mma8(c[0][3], a0, b1[2], b1[3]);
                mma8(c[1][0], a1, b0[0], b0[1]);  mma8(c[1][1], a1, b0[2], b0[3]);
                mma8(c[1][2], a1, b1[0], b1[1]);  mma8(c[1][3], a1, b1[2], b1[3]);
            }

            // ---- exp (no-max) + mask, P -> smem (tf32-rounded f32) ----
            const int n0 = t * FN;
            #pragma unroll
            for (int ma = 0; ma < 2; ma++) {
                float lA = 0.f, lB = 0.f;
                #pragma unroll
                for (int nb = 0; nb < 4; nb++) {
                    const int col = n0 + nb * 8 + 2 * tg;
                    const float mv0 = sm[MK_F + col], mv1 = sm[MK_F + col + 1];
                    const float e00 = __expf(c[ma][nb][0]) * mv0;
                    const float e01 = __expf(c[ma][nb][1]) * mv1;
                    const float e10 = __expf(c[ma][nb][2]) * mv0;
                    const float e11 = __expf(c[ma][nb][3]) * mv1;
                    lA += e00 + e01;
                    lB += e10 + e11;
                    const uint32_t pw = smb +
                        (PS_F + (wid * 32 + ma * 16 + g) * PLD + nb * 8 + 2 * tg) * 4;
                    sts_v2(pw, tf32u(e00), tf32u(e01));
                    sts_v2(pw + 8 * PLD * 4, tf32u(e10), tf32u(e11));
                }
                lgA[ma] += lA;
                lgB[ma] += lB;
            }
        }
        __syncthreads();            // K consumed + P visible

        if (t + 1 < NT) load_Kt(smb, Kb, (t + 1) * FN, tid);
        CP_COMMIT();                // pending: [V_t, K_{t+1}]
        CP_WAIT(1);                 // V_t resident
        __syncthreads();

        // ---- O += P V_t : all 16 warps, m16 x h128 (k8 steps) ----
        #pragma unroll
        for (int ks = 0; ks < 4; ks++) {
            uint32_t a[4];
            ldsm4(a, aP + ks * 32);
            #pragma unroll
            for (int pr = 0; pr < 8; pr++) {
                uint32_t bb[4];
                ldsm4(bb, bV + pr * (16 * VLD * 4) + ks * 32);
                mma8(o[2 * pr + 0], a, bb[0], bb[1]);
                mma8(o[2 * pr + 1], a, bb[2], bb[3]);
            }
        }
        __syncthreads();            // V consumed

        if (t + 1 < NT) load_Vt(smb, Vtb, (t + 1) * FN, tid);
        CP_COMMIT();                // pending: [K_{t+1}, V_{t+1}]
    }

    // ---- l: quad reduce in S-warps, write full row sums ----
    if (wid < 4) {
        #pragma unroll
        for (int ma = 0; ma < 2; ma++) {
            float lA = lgA[ma], lB = lgB[ma];
            lA += __shfl_xor_sync(0xffffffffu, lA, 1);
            lA += __shfl_xor_sync(0xffffffffu, lA, 2);
            lB += __shfl_xor_sync(0xffffffffu, lB, 1);
            lB += __shfl_xor_sync(0xffffffffu, lB, 2);
            if (tg == 0) {
                sm[LR_F + wid * 32 + ma * 16 + g]     = lA;
                sm[LR_F + wid * 32 + ma * 16 + g + 8] = lB;
            }
        }
    }
    __syncthreads();

    const int r0 = mt * 16 + g;
    const float inv0 = 1.f / sm[LR_F + r0];
    const float inv8 = 1.f / sm[LR_F + r0 + 8];

    float* outb = out + ((size_t)b * NA + q0) * HID;
    #pragma unroll
    for (int nb = 0; nb < 16; nb++) {
        const int col = nh * 128 + nb * 8 + 2 * tg;
        float2 v0, v8;
        v0.x = o[nb][0] * inv0; v0.y = o[nb][1] * inv0;
        v8.x = o[nb][2] * inv8; v8.y = o[nb][3] * inv8;
        *(float2*)&outb[(size_t)(r0)     * HID + col] = v0;
        *(float2*)&outb[(size_t)(r0 + 8) * HID + col] = v8;
    }
}

// ---------------------------------------------------------------------------
extern "C" void kernel_launch(void* const* d_in, const int* in_sizes, int n_in,
                              void* d_out, int out_size)
{
    const float* A    = (const float*)d_in[0];
    const float* B    = (const float*)d_in[1];
    const int*   mask = (const int*)  d_in[2];
    const float* Wq   = (const float*)d_in[3];
    const float* bq   = (const float*)d_in[4];
    const float* Wk   = (const float*)d_in[5];
    const float* bk   = (const float*)d_in[6];
    const float* Wv   = (const float*)d_in[7];
    const float* bv   = (const float*)d_in[8];
    float* out = (float*)d_out;

    (void)in_sizes; (void)n_in; (void)out_size;

    cudaFuncSetAttribute(proj_kernel, cudaFuncAttributeMaxDynamicSharedMemorySize,
                         PJ_SMEM_BYTES);
    cudaFuncSetAttribute(attn_kernel, cudaFuncAttributeMaxDynamicSharedMemorySize,
                         SMEM_BYTES);

    round_kernel<<<1024, 256>>>(A, B, Wq, Wk, Wv);

    dim3 pg(NA / 128, HID / 64, 3 * BATCH);
    proj_kernel<<<pg, 256, PJ_SMEM_BYTES>>>(bq, bk, bv);

    dim3 ag(NA / FM, BATCH);
    attn_kernel<<<ag, NTH, SMEM_BYTES>>>(mask, out);
}